// round 6
// baseline (speedup 1.0000x reference)
#include <cuda_runtime.h>
#include <cuda_bf16.h>
#include <cstdint>

#define N_USER 100000
#define N_ITEM 50000
#define N_TOTAL (N_USER + N_ITEM)   // 150000
#define D 64
#define NNZ 4000000
#define B 2048
#define NEG (4 * B)                  // 8192
#define NSLOTS (B + B + NEG)         // 12288
#define NWORDS ((N_TOTAL + 31) / 32) // 4688 words = 18.75 KB bitset
#define MAXDEG 128                   // mean deg ~26.7; P(deg>127) astronomically small

#define EPT 4                        // edges per thread in scan (one int4)
#define SCAN_THREADS 256

// Device scratch. flags are returned to all-zero by K3 each call; rowmap and
// cnt never need resetting (rowmap entries are only read for rows freshly
// claimed this call; cnt[s] is zeroed by its own slot in K1 each call).
__device__ int      g_rowmap[N_TOTAL];                 // row -> owner slot + 1
__device__ int      g_cnt[NSLOTS];                     // edges in owner's bucket
__device__ int2     g_edges[(size_t)NSLOTS * MAXDEG];  // (col, val bits), 12.6 MB
__device__ unsigned g_flags[NWORDS];                   // needed-row bitset (L1-hot)

// slot -> global row id in [0, N_TOTAL)
__device__ __forceinline__ int slot_row(int s, const int* __restrict__ users,
                                        const int* __restrict__ pos,
                                        const int* __restrict__ neg) {
    if (s < B) return users[s];
    if (s < 2 * B) return N_USER + pos[s - B];
    return N_USER + neg[s - 2 * B];
}

// ---------------------------------------------------------------------------
// K1: claim. Racing word stores to rowmap[r] resolve to one winner (any is
// fine: all slots sharing the row read the same final value in K2/K3).
// ---------------------------------------------------------------------------
__global__ void k_claim(const int* __restrict__ users,
                        const int* __restrict__ pos,
                        const int* __restrict__ neg) {
    int s = blockIdx.x * blockDim.x + threadIdx.x;
    if (s >= NSLOTS) return;
    int r = slot_row(s, users, pos, neg);
    g_rowmap[r] = s + 1;
    g_cnt[s] = 0;
    atomicOr(&g_flags[r >> 5], 1u << (r & 31));
}

// ---------------------------------------------------------------------------
// K2: build. Scan all edges (int4 row loads), probe the L1-resident bitset,
// append hits (col, val) to the final owner's bucket.
// ---------------------------------------------------------------------------
__global__ void k_build(const int* __restrict__ adj_row,
                        const int* __restrict__ adj_col,
                        const float* __restrict__ adj_val) {
    int base = (blockIdx.x * SCAN_THREADS + threadIdx.x) * EPT;
    if (base >= NNZ) return;                        // NNZ % 4 == 0 -> full int4
    int4 r4 = __ldg(reinterpret_cast<const int4*>(adj_row) + (base >> 2));
    int rr[EPT] = {r4.x, r4.y, r4.z, r4.w};
#pragma unroll
    for (int k = 0; k < EPT; k++) {
        int r = rr[k];
        if ((__ldg(&g_flags[r >> 5]) >> (r & 31)) & 1u) {
            int   c = __ldg(adj_col + base + k);
            float v = __ldg(adj_val + base + k);
            int owner = g_rowmap[r] - 1;            // final: K1 completed
            int idx = atomicAdd(&g_cnt[owner], 1);
            if (idx < MAXDEG)
                g_edges[(size_t)owner * MAXDEG + idx] =
                    make_int2(c, __float_as_int(v));
        }
    }
}

// ---------------------------------------------------------------------------
// K3: accumulate + blend + write. One warp per slot (dups recompute — cheap).
// Bucket entries are loaded lane-parallel, broadcast via shfl; gathers are
// kept 4-deep in flight. Also resets this row's flag word for the next call.
// ---------------------------------------------------------------------------
__global__ void k_accum(const int* __restrict__ users,
                        const int* __restrict__ pos,
                        const int* __restrict__ neg,
                        const float* __restrict__ user_emb,
                        const float* __restrict__ item_emb,
                        float* __restrict__ out) {
    int gtid = blockIdx.x * blockDim.x + threadIdx.x;
    int warp = gtid >> 5;
    int lane = gtid & 31;
    if (warp >= NSLOTS) return;

    int r = slot_row(warp, users, pos, neg);        // broadcast load
    if (lane == 0) g_flags[r >> 5] = 0u;            // racing zeros — benign
    int owner = g_rowmap[r] - 1;                    // broadcast load
    int cnt = g_cnt[owner];
    cnt = cnt < MAXDEG ? cnt : MAXDEG;
    const int2* bucket = g_edges + (size_t)owner * MAXDEG;

    float ax = 0.0f, ay = 0.0f;

#define PROC(J)                                                              \
    {                                                                        \
        int   cc = __shfl_sync(0xffffffffu, e.x, (J));                       \
        float vv = __int_as_float(__shfl_sync(0xffffffffu, e.y, (J)));       \
        const float* src = (cc < N_USER)                                     \
                               ? (user_emb + (size_t)cc * D)                 \
                               : (item_emb + (size_t)(cc - N_USER) * D);     \
        float2 ev = __ldg(reinterpret_cast<const float2*>(src) + lane);      \
        ax = fmaf(vv, ev.x, ax);                                             \
        ay = fmaf(vv, ev.y, ay);                                             \
    }

    for (int base = 0; base < cnt; base += 32) {
        int rem = cnt - base;
        int m = rem < 32 ? rem : 32;
        int2 e = (lane < m) ? __ldg(bucket + base + lane) : make_int2(0, 0);
        int j = 0;
        for (; j + 4 <= m; j += 4) {
            PROC(j) PROC(j + 1) PROC(j + 2) PROC(j + 3)
        }
        for (; j < m; j++) PROC(j)
    }
#undef PROC

    const float* e0 = (r < N_USER) ? (user_emb + (size_t)r * D)
                                   : (item_emb + (size_t)(r - N_USER) * D);
    float2 e = __ldg(reinterpret_cast<const float2*>(e0) + lane);
    float2 o;
    o.x = (e.x + 3.0f * ax) * 0.25f;
    o.y = (e.y + 3.0f * ay) * 0.25f;
    reinterpret_cast<float2*>(out)[(size_t)warp * (D / 2) + lane] = o;
}

// ---------------------------------------------------------------------------
// launch
// ---------------------------------------------------------------------------
extern "C" void kernel_launch(void* const* d_in, const int* in_sizes, int n_in,
                              void* d_out, int out_size) {
    const int*   users    = (const int*)d_in[0];
    const int*   pos      = (const int*)d_in[1];
    const int*   neg      = (const int*)d_in[2];
    // d_in[3] mask, d_in[4] norm_adj: unused placeholders
    const float* user_emb = (const float*)d_in[5];
    const float* item_emb = (const float*)d_in[6];
    const int*   adj_row  = (const int*)d_in[7];
    const int*   adj_col  = (const int*)d_in[8];
    const float* adj_val  = (const float*)d_in[9];
    float* out = (float*)d_out;

    (void)in_sizes; (void)n_in; (void)out_size;

    {   // K1: claim (1 thread per slot)
        int threads = 256, blocks = (NSLOTS + threads - 1) / threads;
        k_claim<<<blocks, threads>>>(users, pos, neg);
    }
    {   // K2: build buckets (4 edges per thread)
        int blocks = (NNZ + SCAN_THREADS * EPT - 1) / (SCAN_THREADS * EPT);
        k_build<<<blocks, SCAN_THREADS>>>(adj_row, adj_col, adj_val);
    }
    {   // K3: accumulate + blend + write (1 warp per slot) + flag reset
        int threads = 256;
        int blocks = (NSLOTS * 32 + threads - 1) / threads;
        k_accum<<<blocks, threads>>>(users, pos, neg, user_emb, item_emb, out);
    }
}